// round 4
// baseline (speedup 1.0000x reference)
#include <cuda_runtime.h>
#include <cuda_bf16.h>
#include <cstdint>
#include <math.h>

// ---------------------------------------------------------------------------
// Sizes (elements)
//   s_out   (8,128,33,33)   = 1,115,136
//   t_out   (8,768,65,65)   = 25,958,400
//   t_logit (8,19,65,65)    = 642,200
//   s_logit (8,19,129,129)  = 2,529,912
//   conv_w  (768,128,1,1)   = 98,304
//   conv_b  (768,)          = 768
// Output: 2 floats (pi_loss, lo_loss)
// ---------------------------------------------------------------------------
#define PIX33 1089
#define PIX65 4225
#define PIX129 16641
#define CIN 128
#define COUT 768
#define NB 8
#define NCH 19

__device__ __align__(16) float g_Wt[CIN * COUT];          // W transposed [c][o]
__device__ __align__(16) float g_y33[NB * COUT * PIX33];  // conv out @33x33 [b][o][pix]
__device__ __align__(16) float g_Ut[NB * NCH * PIX129];   // exp(interp t_logit)
__device__ __align__(16) float g_Us[NB * NCH * PIX129];   // exp(s_logit)
__device__ double g_pi;
__device__ double g_d[2][NB * NCH];     // sum exp   (side 0=s, 1=t)
__device__ double g_Wz[2][NB * NCH];    // sum exp*z
__device__ double g_R[2][NB][190];      // Gram upper-tri pairs

// ---------------------------------------------------------------------------
__global__ void zero_kernel() {
    int t = blockIdx.x * blockDim.x + threadIdx.x;
    if (t == 0) g_pi = 0.0;
    if (t < NB * NCH) {
        g_d[0][t] = 0.0; g_d[1][t] = 0.0;
        g_Wz[0][t] = 0.0; g_Wz[1][t] = 0.0;
    }
    if (t < 2 * NB * 190) ((double*)g_R)[t] = 0.0;
}

__global__ void transpose_w_kernel(const float* __restrict__ conv_w) {
    int idx = blockIdx.x * blockDim.x + threadIdx.x;   // idx = c*768 + o
    if (idx < CIN * COUT) {
        int c = idx / COUT, o = idx - c * COUT;
        g_Wt[idx] = conv_w[o * CIN + c];
    }
}

// ---------------------------------------------------------------------------
// GEMM: y33[b][o][pix] = sum_c s_out[b][c][pix] * W[o][c] + bias[o]
// ---------------------------------------------------------------------------
__global__ void gemm_kernel(const float* __restrict__ s_out,
                            const float* __restrict__ bias) {
    int b    = blockIdx.z;
    int pix0 = blockIdx.x * 64;
    int o0   = blockIdx.y * 64;
    int tx = threadIdx.x, ty = threadIdx.y;
    int tid = ty * 16 + tx;

    __shared__ __align__(16) float As[16][64];
    __shared__ __align__(16) float Bs[16][64];

    float acc[4][4] = {};

    const float* Ab = s_out + (size_t)b * CIN * PIX33;

    int kk = tid >> 4;
    int mm = (tid & 15) * 4;

    for (int k0 = 0; k0 < CIN; k0 += 16) {
        const float* arow = Ab + (size_t)(k0 + kk) * PIX33;
#pragma unroll
        for (int u = 0; u < 4; u++) {
            int pix = pix0 + mm + u;
            As[kk][mm + u] = (pix < PIX33) ? arow[pix] : 0.f;
        }
        *(float4*)&Bs[kk][mm] =
            *(const float4*)&g_Wt[(size_t)(k0 + kk) * COUT + o0 + mm];
        __syncthreads();

#pragma unroll
        for (int k2 = 0; k2 < 16; k2++) {
            float4 a4 = *(const float4*)&As[k2][tx * 4];
            float4 b4 = *(const float4*)&Bs[k2][ty * 4];
            float av[4] = {a4.x, a4.y, a4.z, a4.w};
            float bv[4] = {b4.x, b4.y, b4.z, b4.w};
#pragma unroll
            for (int i = 0; i < 4; i++)
#pragma unroll
                for (int j = 0; j < 4; j++)
                    acc[i][j] += av[i] * bv[j];
        }
        __syncthreads();
    }

#pragma unroll
    for (int j = 0; j < 4; j++) {
        int o = o0 + ty * 4 + j;
        float bb = bias[o];
        float* orow = g_y33 + ((size_t)b * COUT + o) * PIX33;
#pragma unroll
        for (int i = 0; i < 4; i++) {
            int pix = pix0 + tx * 4 + i;
            if (pix < PIX33) orow[pix] = acc[i][j] + bb;
        }
    }
}

// ---------------------------------------------------------------------------
// pi kernel: per 65x65 pixel:
//   St1=sum e^zt, St2=sum zt e^zt, St3=sum zs e^zt, Ss=sum e^zs
//   pixel_KL = St2/St1 - log(St1) - St3/St1 + log(Ss)
// ---------------------------------------------------------------------------
__global__ void pi_kernel(const float* __restrict__ t_out) {
    int b  = blockIdx.y;
    int tx = threadIdx.x, ty = threadIdx.y;
    int p  = blockIdx.x * 32 + tx;
    bool valid = (p < PIX65);
    int pp = valid ? p : 0;

    int y = pp / 65, x = pp - y * 65;
    int y0 = y >> 1, x0 = x >> 1;
    int y1 = min(y0 + 1, 32), x1 = min(x0 + 1, 32);
    float wy = (y & 1) * 0.5f, wx = (x & 1) * 0.5f;
    float w00 = (1.f - wy) * (1.f - wx);
    float w01 = (1.f - wy) * wx;
    float w10 = wy * (1.f - wx);
    float w11 = wy * wx;
    int i00 = y0 * 33 + x0, i01 = y0 * 33 + x1;
    int i10 = y1 * 33 + x0, i11 = y1 * 33 + x1;
    bool nx = (wx > 0.f), ny = (wy > 0.f);

    const float* tb = t_out + (size_t)b * COUT * PIX65 + pp;
    const float* yb = g_y33 + (size_t)b * COUT * PIX33;

    float S1 = 0.f, S2 = 0.f, S3 = 0.f, Ss = 0.f;
    if (valid) {
        for (int c = ty; c < COUT; c += 8) {
            float zt = tb[(size_t)c * PIX65];
            const float* Y = yb + (size_t)c * PIX33;
            float zs = w00 * Y[i00];
            if (nx) zs += w01 * Y[i01];
            if (ny) {
                zs += w10 * Y[i10];
                if (nx) zs += w11 * Y[i11];
            }
            float e = __expf(zt);
            S1 += e;
            S2 += zt * e;
            S3 += zs * e;
            Ss += __expf(zs);
        }
    }

    __shared__ float r1[8][32], r2[8][32], r3[8][32], rs[8][32];
    r1[ty][tx] = S1; r2[ty][tx] = S2; r3[ty][tx] = S3; rs[ty][tx] = Ss;
    __syncthreads();

    if (ty == 0) {
#pragma unroll
        for (int u = 1; u < 8; u++) {
            S1 += r1[u][tx]; S2 += r2[u][tx];
            S3 += r3[u][tx]; Ss += rs[u][tx];
        }
        float psum = 0.f;
        if (valid) {
            float inv = 1.f / S1;
            psum = S2 * inv - logf(S1) - S3 * inv + logf(Ss);
        }
#pragma unroll
        for (int o = 16; o; o >>= 1)
            psum += __shfl_down_sync(0xFFFFFFFFu, psum, o);
        if (tx == 0) atomicAdd(&g_pi, (double)psum);
    }
}

// ---------------------------------------------------------------------------
// lo prep: U=exp(z) to scratch; accumulate d=sum U, Wz=sum U*z per (b,ch).
// ---------------------------------------------------------------------------
__device__ __forceinline__ void prep_reduce_store(float dloc, float wloc,
                                                  int side, int row) {
    __shared__ float rd[256], rw[256];
    int tid = threadIdx.x;
    rd[tid] = dloc; rw[tid] = wloc;
    __syncthreads();
    for (int o = 128; o; o >>= 1) {
        if (tid < o) { rd[tid] += rd[tid + o]; rw[tid] += rw[tid + o]; }
        __syncthreads();
    }
    if (tid == 0) {
        atomicAdd(&g_d[side][row], (double)rd[0]);
        atomicAdd(&g_Wz[side][row], (double)rw[0]);
    }
}

__global__ void tprep_kernel(const float* __restrict__ t_logit) {
    int row = blockIdx.y;                        // b*19 + ch
    int k = blockIdx.x * 256 + threadIdx.x;
    float dloc = 0.f, wloc = 0.f;
    if (k < PIX129) {
        int y = k / 129, x = k - y * 129;
        int y0 = y >> 1, x0 = x >> 1;
        int y1 = min(y0 + 1, 64), x1 = min(x0 + 1, 64);
        float wy = (y & 1) * 0.5f, wx = (x & 1) * 0.5f;
        const float* src = t_logit + (size_t)row * PIX65;
        float top = (1.f - wx) * src[y0 * 65 + x0] + wx * src[y0 * 65 + x1];
        float bot = (1.f - wx) * src[y1 * 65 + x0] + wx * src[y1 * 65 + x1];
        float z = (1.f - wy) * top + wy * bot;
        float u = __expf(z);
        g_Ut[(size_t)row * PIX129 + k] = u;
        dloc = u; wloc = u * z;
    }
    prep_reduce_store(dloc, wloc, 1, row);
}

__global__ void sprep_kernel(const float* __restrict__ s_logit) {
    int row = blockIdx.y;
    int k = blockIdx.x * 256 + threadIdx.x;
    float dloc = 0.f, wloc = 0.f;
    if (k < PIX129) {
        float z = s_logit[(size_t)row * PIX129 + k];
        float u = __expf(z);
        g_Us[(size_t)row * PIX129 + k] = u;
        dloc = u; wloc = u * z;
    }
    prep_reduce_store(dloc, wloc, 0, row);
}

// ---------------------------------------------------------------------------
// Gram: R[side][b][pair] += sum_k U_i[k]*U_j[k] over one 512-chunk of k.
// ---------------------------------------------------------------------------
__global__ void gram_kernel() {
    int side = blockIdx.z;   // 0=s, 1=t
    int b    = blockIdx.y;
    int k0   = blockIdx.x * 512;
    const float* U = (side ? g_Ut : g_Us) + (size_t)b * NCH * PIX129;

    __shared__ float sm[NCH][513];
    int tid = threadIdx.x;
    for (int idx = tid; idx < NCH * 512; idx += 256) {
        int i = idx >> 9, kk = idx & 511;
        int k = k0 + kk;
        sm[i][kk] = (k < PIX129) ? U[(size_t)i * PIX129 + k] : 0.f;
    }
    __syncthreads();

    if (tid < 190) {
        int i = 0, t = tid;
        while (t >= NCH - i) { t -= NCH - i; i++; }
        int j = i + t;
        const float* ri = sm[i];
        const float* rj = sm[j];
        float acc = 0.f;
#pragma unroll 4
        for (int kk = 0; kk < 512; kk++) acc += ri[kk] * rj[kk];
        atomicAdd(&g_R[side][b][tid], (double)acc);
    }
}

// ---------------------------------------------------------------------------
// Finalize: ICC matrices, lo_loss, pi_loss.
// ---------------------------------------------------------------------------
__global__ void finalize_kernel(float* __restrict__ out) {
    int tid = threadIdx.x;
    __shared__ double sE[2][NCH];
    __shared__ double sG[2][361];
    __shared__ double sS[2][361];
    __shared__ double sN[2][NCH];
    __shared__ double red[512];

    if (tid < 2 * NCH) {
        int side = tid / NCH, i = tid % NCH;
        double e = 0.0;
        for (int b = 0; b < NB; b++) {
            double d = g_d[side][b * NCH + i];
            e += g_Wz[side][b * NCH + i] / d - log(d);
        }
        sE[side][i] = e;
    }
    if (tid < 361) {
        int i = tid / NCH, j = tid % NCH;
        int mi = min(i, j), mj = max(i, j);
        int p = mi * NCH - mi * (mi - 1) / 2 + (mj - mi);
        for (int side = 0; side < 2; side++) {
            double g = 0.0;
            for (int b = 0; b < NB; b++)
                g += g_R[side][b][p] /
                     (g_d[side][b * NCH + i] * g_d[side][b * NCH + j]);
            sG[side][tid] = g;
        }
    }
    __syncthreads();
    if (tid < 361) {
        int i = tid / NCH, j = tid % NCH;
        int mx = max(i, j);
        sS[0][tid] = (sE[0][mx] - sG[0][tid]) / (double)NB;
        sS[1][tid] = (sE[1][mx] - sG[1][tid]) / (double)NB;
    }
    __syncthreads();
    if (tid < 2 * NCH) {
        int side = tid / NCH, i = tid % NCH;
        double s = 0.0;
        for (int j = 0; j < NCH; j++) {
            double v = sS[side][i * NCH + j];
            s += v * v;
        }
        double n = sqrt(s);
        sN[side][i] = (n > 1e-12) ? n : 1e-12;
    }
    __syncthreads();
    double v = 0.0;
    if (tid < 361) {
        int i = tid / NCH;
        double dd = sS[0][tid] / sN[0][i] - sS[1][tid] / sN[1][i];
        v = dd * dd;
    }
    red[tid] = v;
    __syncthreads();
    for (int o = 256; o; o >>= 1) {
        if (tid < o) red[tid] += red[tid + o];
        __syncthreads();
    }
    if (tid == 0) {
        out[0] = (float)(g_pi / 25958400.0);
        out[1] = (float)red[0];
    }
}

// ---------------------------------------------------------------------------
extern "C" void kernel_launch(void* const* d_in, const int* in_sizes, int n_in,
                              void* d_out, int out_size) {
    const float *ptr[6] = {nullptr, nullptr, nullptr, nullptr, nullptr, nullptr};
    const int want[6] = {1115136, 25958400, 642200, 2529912, 98304, 768};

    // Tier 1+2: size matching, accepting element counts OR byte counts.
    for (int i = 0; i < n_in; i++) {
        long long s = in_sizes[i];
        for (int k = 0; k < 6; k++) {
            if (s == (long long)want[k] || s == 4LL * want[k]) {
                if (!ptr[k]) ptr[k] = (const float*)d_in[i];
            }
        }
    }
    // Tier 3: positional fallback in reference-signature order.
    if (n_in >= 6) {
        for (int k = 0; k < 6; k++)
            if (!ptr[k]) ptr[k] = (const float*)d_in[k];
    }

    const float* s_out   = ptr[0];
    const float* t_out   = ptr[1];
    const float* t_logit = ptr[2];
    const float* s_logit = ptr[3];
    const float* conv_w  = ptr[4];
    const float* conv_b  = ptr[5];

    zero_kernel<<<15, 256>>>();
    transpose_w_kernel<<<(CIN * COUT + 255) / 256, 256>>>(conv_w);
    gemm_kernel<<<dim3(18, 12, NB), dim3(16, 16)>>>(s_out, conv_b);
    pi_kernel<<<dim3((PIX65 + 31) / 32, NB), dim3(32, 8)>>>(t_out);
    tprep_kernel<<<dim3((PIX129 + 255) / 256, NB * NCH), 256>>>(t_logit);
    sprep_kernel<<<dim3((PIX129 + 255) / 256, NB * NCH), 256>>>(s_logit);
    gram_kernel<<<dim3((PIX129 + 511) / 512, NB, 2), 256>>>();
    finalize_kernel<<<1, 512>>>((float*)d_out);
}

// round 5
// speedup vs baseline: 1.2009x; 1.2009x over previous
#include <cuda_runtime.h>
#include <cuda_bf16.h>
#include <cstdint>
#include <math.h>

// ---------------------------------------------------------------------------
// Sizes (elements)
//   s_out   (8,128,33,33)   = 1,115,136
//   t_out   (8,768,65,65)   = 25,958,400
//   t_logit (8,19,65,65)    = 642,200
//   s_logit (8,19,129,129)  = 2,529,912
//   conv_w  (768,128,1,1)   = 98,304
//   conv_b  (768,)          = 768
// ---------------------------------------------------------------------------
#define PIX33 1089
#define PITCH33 1092           // padded row pitch for y33 (16B-aligned rows)
#define PIX65 4225
#define PIX129 16641
#define CIN 128
#define COUT 768
#define NB 8
#define NCH 19
#define NSLICE 4               // channel slices for pi partial kernel

__device__ __align__(16) float g_Wt[CIN * COUT];            // W transposed [c][o]
__device__ __align__(16) float g_y33[NB * COUT * PITCH33];  // conv out @33x33 [b][o][pitched pix]
__device__ __align__(16) float g_Ut[NB * NCH * PIX129];     // exp(interp t_logit)
__device__ __align__(16) float g_Us[NB * NCH * PIX129];     // exp(s_logit)
__device__ __align__(16) float g_part[NSLICE][NB][4][PIX65];// pi partial stats
__device__ double g_pi;
__device__ double g_d[2][NB * NCH];
__device__ double g_Wz[2][NB * NCH];
__device__ double g_R[2][NB][190];

// ---------------------------------------------------------------------------
__global__ void zero_kernel() {
    int t = blockIdx.x * blockDim.x + threadIdx.x;
    if (t == 0) g_pi = 0.0;
    if (t < NB * NCH) {
        g_d[0][t] = 0.0; g_d[1][t] = 0.0;
        g_Wz[0][t] = 0.0; g_Wz[1][t] = 0.0;
    }
    if (t < 2 * NB * 190) ((double*)g_R)[t] = 0.0;
}

__global__ void transpose_w_kernel(const float* __restrict__ conv_w) {
    int idx = blockIdx.x * blockDim.x + threadIdx.x;   // idx = c*768 + o
    if (idx < CIN * COUT) {
        int c = idx / COUT, o = idx - c * COUT;
        g_Wt[idx] = conv_w[o * CIN + c];
    }
}

// ---------------------------------------------------------------------------
// GEMM: y33[b][o][pix] = sum_c s_out[b][c][pix] * W[o][c] + bias[o]
// 128x128 tile, 8x8 register tile, K step 16. Block = 256 threads.
// ---------------------------------------------------------------------------
__global__ __launch_bounds__(256) void gemm_kernel(const float* __restrict__ s_out,
                                                   const float* __restrict__ bias) {
    int b    = blockIdx.z;
    int pix0 = blockIdx.x * 128;   // 9 tiles over 1089
    int o0   = blockIdx.y * 128;   // 6 tiles over 768

    __shared__ __align__(16) float As[16][128];
    __shared__ __align__(16) float Bs[16][128];

    int tid = threadIdx.x;
    int tx = tid & 15, ty = tid >> 4;

    float acc[8][8];
#pragma unroll
    for (int i = 0; i < 8; i++)
#pragma unroll
        for (int j = 0; j < 8; j++) acc[i][j] = 0.f;

    const float* Ab = s_out + (size_t)b * CIN * PIX33;
    int kk = tid >> 4;          // 0..15
    int m0 = (tid & 15) * 8;    // 0..120

    for (int k0 = 0; k0 < CIN; k0 += 16) {
        const float* arow = Ab + (size_t)(k0 + kk) * PIX33;
#pragma unroll
        for (int u = 0; u < 8; u++) {
            int pix = pix0 + m0 + u;
            As[kk][m0 + u] = (pix < PIX33) ? arow[pix] : 0.f;
        }
        const float* brow = g_Wt + (size_t)(k0 + kk) * COUT + o0 + m0;
        *(float4*)&Bs[kk][m0]     = *(const float4*)brow;
        *(float4*)&Bs[kk][m0 + 4] = *(const float4*)(brow + 4);
        __syncthreads();

#pragma unroll
        for (int k2 = 0; k2 < 16; k2++) {
            float4 a0 = *(const float4*)&As[k2][tx * 4];
            float4 a1 = *(const float4*)&As[k2][64 + tx * 4];
            float4 b0 = *(const float4*)&Bs[k2][ty * 4];
            float4 b1 = *(const float4*)&Bs[k2][64 + ty * 4];
            float av[8] = {a0.x, a0.y, a0.z, a0.w, a1.x, a1.y, a1.z, a1.w};
            float bv[8] = {b0.x, b0.y, b0.z, b0.w, b1.x, b1.y, b1.z, b1.w};
#pragma unroll
            for (int i = 0; i < 8; i++)
#pragma unroll
                for (int j = 0; j < 8; j++)
                    acc[i][j] += av[i] * bv[j];
        }
        __syncthreads();
    }

#pragma unroll
    for (int jj = 0; jj < 8; jj++) {
        int o = o0 + ((jj < 4) ? (ty * 4 + jj) : (64 + ty * 4 + jj - 4));
        float bb = bias[o];
        float* orow = g_y33 + ((size_t)b * COUT + o) * PITCH33;
#pragma unroll
        for (int g = 0; g < 2; g++) {
            int p = pix0 + g * 64 + tx * 4;
            float v0 = acc[g * 4 + 0][jj] + bb;
            float v1 = acc[g * 4 + 1][jj] + bb;
            float v2 = acc[g * 4 + 2][jj] + bb;
            float v3 = acc[g * 4 + 3][jj] + bb;
            if (p + 3 < PIX33) {
                float4 v = make_float4(v0, v1, v2, v3);
                *(float4*)&orow[p] = v;
            } else {
                if (p + 0 < PIX33) orow[p + 0] = v0;
                if (p + 1 < PIX33) orow[p + 1] = v1;
                if (p + 2 < PIX33) orow[p + 2] = v2;
                if (p + 3 < PIX33) orow[p + 3] = v3;
            }
        }
    }
}

// ---------------------------------------------------------------------------
// pi partial: each block handles 32 pixels x 192 channels (one slice).
// Stats: S1=sum e^zt, S2=sum zt e^zt, S3=sum zs e^zt, Ss=sum e^zs.
// ---------------------------------------------------------------------------
__global__ void pi_partial_kernel(const float* __restrict__ t_out) {
    int b     = blockIdx.y;
    int slice = blockIdx.z;
    int tx = threadIdx.x, ty = threadIdx.y;
    int p  = blockIdx.x * 32 + tx;
    bool valid = (p < PIX65);
    int pp = valid ? p : 0;

    int y = pp / 65, x = pp - y * 65;
    int y0 = y >> 1, x0 = x >> 1;
    int y1 = min(y0 + 1, 32), x1 = min(x0 + 1, 32);
    float wy = (y & 1) * 0.5f, wx = (x & 1) * 0.5f;
    float w00 = (1.f - wy) * (1.f - wx);
    float w01 = (1.f - wy) * wx;
    float w10 = wy * (1.f - wx);
    float w11 = wy * wx;
    int i00 = y0 * 33 + x0, i01 = y0 * 33 + x1;
    int i10 = y1 * 33 + x0, i11 = y1 * 33 + x1;
    bool nx = (wx > 0.f), ny = (wy > 0.f);

    const float* tb = t_out + (size_t)b * COUT * PIX65 + pp;
    const float* yb = g_y33 + (size_t)b * COUT * PITCH33
                    + (size_t)(slice * 192) * PITCH33;
    const float* tbs = tb + (size_t)(slice * 192) * PIX65;

    float S1 = 0.f, S2 = 0.f, S3 = 0.f, Ss = 0.f;
    if (valid) {
#pragma unroll 4
        for (int k = 0; k < 24; k++) {
            int c = ty + k * 8;                    // 0..191 within slice
            float zt = tbs[(size_t)c * PIX65];
            const float* Y = yb + (size_t)c * PITCH33;
            float zs = w00 * Y[i00];
            if (nx) zs += w01 * Y[i01];
            if (ny) {
                zs += w10 * Y[i10];
                if (nx) zs += w11 * Y[i11];
            }
            float e = __expf(zt);
            S1 += e;
            S2 += zt * e;
            S3 += zs * e;
            Ss += __expf(zs);
        }
    }

    __shared__ float r1[8][32], r2[8][32], r3[8][32], rs[8][32];
    r1[ty][tx] = S1; r2[ty][tx] = S2; r3[ty][tx] = S3; rs[ty][tx] = Ss;
    __syncthreads();

    if (ty == 0 && valid) {
#pragma unroll
        for (int u = 1; u < 8; u++) {
            S1 += r1[u][tx]; S2 += r2[u][tx];
            S3 += r3[u][tx]; Ss += rs[u][tx];
        }
        g_part[slice][b][0][p] = S1;
        g_part[slice][b][1][p] = S2;
        g_part[slice][b][2][p] = S3;
        g_part[slice][b][3][p] = Ss;
    }
}

// ---------------------------------------------------------------------------
// pi final: combine slices, per-pixel KL, reduce into g_pi.
// ---------------------------------------------------------------------------
__global__ void pi_final_kernel() {
    int b = blockIdx.y;
    int p = blockIdx.x * 256 + threadIdx.x;
    float v = 0.f;
    if (p < PIX65) {
        float S1 = 0.f, S2 = 0.f, S3 = 0.f, Ss = 0.f;
#pragma unroll
        for (int s = 0; s < NSLICE; s++) {
            S1 += g_part[s][b][0][p];
            S2 += g_part[s][b][1][p];
            S3 += g_part[s][b][2][p];
            Ss += g_part[s][b][3][p];
        }
        float inv = 1.f / S1;
        v = S2 * inv - logf(S1) - S3 * inv + logf(Ss);
    }
    __shared__ float red[256];
    int tid = threadIdx.x;
    red[tid] = v;
    __syncthreads();
    for (int o = 128; o; o >>= 1) {
        if (tid < o) red[tid] += red[tid + o];
        __syncthreads();
    }
    if (tid == 0) atomicAdd(&g_pi, (double)red[0]);
}

// ---------------------------------------------------------------------------
// lo prep: U=exp(z) to scratch; accumulate d=sum U, Wz=sum U*z per (b,ch).
// ---------------------------------------------------------------------------
__device__ __forceinline__ void prep_reduce_store(float dloc, float wloc,
                                                  int side, int row) {
    __shared__ float rd[256], rw[256];
    int tid = threadIdx.x;
    rd[tid] = dloc; rw[tid] = wloc;
    __syncthreads();
    for (int o = 128; o; o >>= 1) {
        if (tid < o) { rd[tid] += rd[tid + o]; rw[tid] += rw[tid + o]; }
        __syncthreads();
    }
    if (tid == 0) {
        atomicAdd(&g_d[side][row], (double)rd[0]);
        atomicAdd(&g_Wz[side][row], (double)rw[0]);
    }
}

__global__ void tprep_kernel(const float* __restrict__ t_logit) {
    int row = blockIdx.y;                        // b*19 + ch
    int k = blockIdx.x * 256 + threadIdx.x;
    float dloc = 0.f, wloc = 0.f;
    if (k < PIX129) {
        int y = k / 129, x = k - y * 129;
        int y0 = y >> 1, x0 = x >> 1;
        int y1 = min(y0 + 1, 64), x1 = min(x0 + 1, 64);
        float wy = (y & 1) * 0.5f, wx = (x & 1) * 0.5f;
        const float* src = t_logit + (size_t)row * PIX65;
        float top = (1.f - wx) * src[y0 * 65 + x0] + wx * src[y0 * 65 + x1];
        float bot = (1.f - wx) * src[y1 * 65 + x0] + wx * src[y1 * 65 + x1];
        float z = (1.f - wy) * top + wy * bot;
        float u = __expf(z);
        g_Ut[(size_t)row * PIX129 + k] = u;
        dloc = u; wloc = u * z;
    }
    prep_reduce_store(dloc, wloc, 1, row);
}

__global__ void sprep_kernel(const float* __restrict__ s_logit) {
    int row = blockIdx.y;
    int k = blockIdx.x * 256 + threadIdx.x;
    float dloc = 0.f, wloc = 0.f;
    if (k < PIX129) {
        float z = s_logit[(size_t)row * PIX129 + k];
        float u = __expf(z);
        g_Us[(size_t)row * PIX129 + k] = u;
        dloc = u; wloc = u * z;
    }
    prep_reduce_store(dloc, wloc, 0, row);
}

// ---------------------------------------------------------------------------
// Gram: R[side][b][pair] += sum_k U_i[k]*U_j[k] over one 512-chunk of k.
// ---------------------------------------------------------------------------
__global__ void gram_kernel() {
    int side = blockIdx.z;
    int b    = blockIdx.y;
    int k0   = blockIdx.x * 512;
    const float* U = (side ? g_Ut : g_Us) + (size_t)b * NCH * PIX129;

    __shared__ float sm[NCH][513];
    int tid = threadIdx.x;
    for (int idx = tid; idx < NCH * 512; idx += 256) {
        int i = idx >> 9, kk = idx & 511;
        int k = k0 + kk;
        sm[i][kk] = (k < PIX129) ? U[(size_t)i * PIX129 + k] : 0.f;
    }
    __syncthreads();

    if (tid < 190) {
        int i = 0, t = tid;
        while (t >= NCH - i) { t -= NCH - i; i++; }
        int j = i + t;
        const float* ri = sm[i];
        const float* rj = sm[j];
        float acc = 0.f;
#pragma unroll 4
        for (int kk = 0; kk < 512; kk++) acc += ri[kk] * rj[kk];
        atomicAdd(&g_R[side][b][tid], (double)acc);
    }
}

// ---------------------------------------------------------------------------
// Finalize: ICC matrices, lo_loss, pi_loss.
// ---------------------------------------------------------------------------
__global__ void finalize_kernel(float* __restrict__ out) {
    int tid = threadIdx.x;
    __shared__ double sE[2][NCH];
    __shared__ double sG[2][361];
    __shared__ double sS[2][361];
    __shared__ double sN[2][NCH];
    __shared__ double red[512];

    if (tid < 2 * NCH) {
        int side = tid / NCH, i = tid % NCH;
        double e = 0.0;
        for (int b = 0; b < NB; b++) {
            double d = g_d[side][b * NCH + i];
            e += g_Wz[side][b * NCH + i] / d - log(d);
        }
        sE[side][i] = e;
    }
    if (tid < 361) {
        int i = tid / NCH, j = tid % NCH;
        int mi = min(i, j), mj = max(i, j);
        int p = mi * NCH - mi * (mi - 1) / 2 + (mj - mi);
        for (int side = 0; side < 2; side++) {
            double g = 0.0;
            for (int b = 0; b < NB; b++)
                g += g_R[side][b][p] /
                     (g_d[side][b * NCH + i] * g_d[side][b * NCH + j]);
            sG[side][tid] = g;
        }
    }
    __syncthreads();
    if (tid < 361) {
        int i = tid / NCH, j = tid % NCH;
        int mx = max(i, j);
        sS[0][tid] = (sE[0][mx] - sG[0][tid]) / (double)NB;
        sS[1][tid] = (sE[1][mx] - sG[1][tid]) / (double)NB;
    }
    __syncthreads();
    if (tid < 2 * NCH) {
        int side = tid / NCH, i = tid % NCH;
        double s = 0.0;
        for (int j = 0; j < NCH; j++) {
            double v = sS[side][i * NCH + j];
            s += v * v;
        }
        double n = sqrt(s);
        sN[side][i] = (n > 1e-12) ? n : 1e-12;
    }
    __syncthreads();
    double v = 0.0;
    if (tid < 361) {
        int i = tid / NCH;
        double dd = sS[0][tid] / sN[0][i] - sS[1][tid] / sN[1][i];
        v = dd * dd;
    }
    red[tid] = v;
    __syncthreads();
    for (int o = 256; o; o >>= 1) {
        if (tid < o) red[tid] += red[tid + o];
        __syncthreads();
    }
    if (tid == 0) {
        out[0] = (float)(g_pi / 25958400.0);
        out[1] = (float)red[0];
    }
}

// ---------------------------------------------------------------------------
extern "C" void kernel_launch(void* const* d_in, const int* in_sizes, int n_in,
                              void* d_out, int out_size) {
    const float *ptr[6] = {nullptr, nullptr, nullptr, nullptr, nullptr, nullptr};
    const int want[6] = {1115136, 25958400, 642200, 2529912, 98304, 768};

    for (int i = 0; i < n_in; i++) {
        long long s = in_sizes[i];
        for (int k = 0; k < 6; k++) {
            if (s == (long long)want[k] || s == 4LL * want[k]) {
                if (!ptr[k]) ptr[k] = (const float*)d_in[i];
            }
        }
    }
    if (n_in >= 6) {
        for (int k = 0; k < 6; k++)
            if (!ptr[k]) ptr[k] = (const float*)d_in[k];
    }

    const float* s_out   = ptr[0];
    const float* t_out   = ptr[1];
    const float* t_logit = ptr[2];
    const float* s_logit = ptr[3];
    const float* conv_w  = ptr[4];
    const float* conv_b  = ptr[5];

    zero_kernel<<<15, 256>>>();
    transpose_w_kernel<<<(CIN * COUT + 255) / 256, 256>>>(conv_w);
    gemm_kernel<<<dim3(9, 6, NB), 256>>>(s_out, conv_b);
    pi_partial_kernel<<<dim3((PIX65 + 31) / 32, NB, NSLICE), dim3(32, 8)>>>(t_out);
    pi_final_kernel<<<dim3((PIX65 + 255) / 256, NB), 256>>>();
    tprep_kernel<<<dim3((PIX129 + 255) / 256, NB * NCH), 256>>>(t_logit);
    sprep_kernel<<<dim3((PIX129 + 255) / 256, NB * NCH), 256>>>(s_logit);
    gram_kernel<<<dim3((PIX129 + 511) / 512, NB, 2), 256>>>();
    finalize_kernel<<<1, 512>>>((float*)d_out);
}